// round 4
// baseline (speedup 1.0000x reference)
#include <cuda_runtime.h>
#include <cstdint>
#include <math.h>

#define BB 2
#define SS 2049
#define EE 512
#define HH 8
#define WINW 1024
#define MROWS (BB * SS)                  // 4098
#define SCALE 0.125f                     // D^-0.5
#define BIASC (-1.9073486328125e-6f)     // -0.5/(512^2)
#define LOG2E 1.4426950408889634f

// Scratch (device globals: no allocation allowed)
__device__ float g_q[MROWS * EE];
__device__ float g_k[MROWS * EE];
__device__ float g_v[MROWS * EE];
__device__ float g_ao[MROWS * EE];
__device__ float g_gq[MROWS];
__device__ float g_gk[MROWS];

// ============================================================================
// helpers
// ============================================================================
__device__ __forceinline__ float tf32r(float x) {
    uint32_t u;
    asm("cvt.rna.tf32.f32 %0, %1;" : "=r"(u) : "f"(x));
    return __uint_as_float(u);
}
__device__ __forceinline__ void split2(float x, float& hi, float& lo) {
    hi = tf32r(x);
    lo = tf32r(x - hi);
}
__device__ __forceinline__ void mma_tf32(float* d, const uint32_t* a, const uint32_t* b) {
    asm volatile(
        "mma.sync.aligned.m16n8k8.row.col.f32.tf32.tf32.f32 "
        "{%0,%1,%2,%3}, {%4,%5,%6,%7}, {%8,%9}, {%0,%1,%2,%3};"
        : "+f"(d[0]), "+f"(d[1]), "+f"(d[2]), "+f"(d[3])
        : "r"(a[0]), "r"(a[1]), "r"(a[2]), "r"(a[3]), "r"(b[0]), "r"(b[1]));
}
__device__ __forceinline__ float rcpf(float x) {
    float r;
    asm("rcp.approx.f32 %0, %1;" : "=f"(r) : "f"(x));
    return r;
}
__device__ __forceinline__ float ex2f(float x) {
    float r;
    asm("ex2.approx.f32 %0, %1;" : "=f"(r) : "f"(x));
    return r;
}
// column-pair permutation: (d, d+4) -> adjacent words
__device__ __forceinline__ int pcol(int d) {
    return ((d >> 3) << 3) | ((d & 3) << 1) | ((d >> 2) & 1);
}

// ---------------------------------------------------------------------------
// 3xTF32 GEMM: C[M,512] = A[M,512] @ B[512,512] + bias
// BM=128 BN=64 BK=16, 256 threads (8 warps: 4M x 2N), warp tile 32x32, occ 2
// ---------------------------------------------------------------------------
#define GASTR 136
#define GBSTR 72
__global__ __launch_bounds__(256, 2) void gemm_tc_kernel(
    const float* __restrict__ A, const float* __restrict__ B,
    const float* __restrict__ bias, float* __restrict__ C, int M)
{
    __shared__ float Ah[16][GASTR], Al[16][GASTR];
    __shared__ float Bh[16][GBSTR], Bl[16][GBSTR];

    const int tid = threadIdx.x;
    const int wid = tid >> 5, lane = tid & 31;
    const int g = lane >> 2, tg = lane & 3;
    const int wm = wid >> 1, wn = wid & 1;
    const int row0 = blockIdx.y * 128, col0 = blockIdx.x * 64;
    const int wrow = wm * 32, wcol = wn * 32;

    float acc[2][4][4];
#pragma unroll
    for (int mt = 0; mt < 2; mt++)
#pragma unroll
        for (int nt = 0; nt < 4; nt++)
#pragma unroll
            for (int e = 0; e < 4; e++) acc[mt][nt][e] = 0.f;

    for (int k0 = 0; k0 < 512; k0 += 16) {
        // stage A: 128 rows x 16 cols, transposed to [k][m]
#pragma unroll
        for (int it = 0; it < 2; it++) {
            int idx = it * 256 + tid;
            int r = idx >> 2, c4 = (idx & 3) * 4;
            float4 v = make_float4(0.f, 0.f, 0.f, 0.f);
            if (row0 + r < M)
                v = *(const float4*)&A[(size_t)(row0 + r) * 512 + k0 + c4];
            float h, l;
            split2(v.x, h, l); Ah[c4 + 0][r] = h; Al[c4 + 0][r] = l;
            split2(v.y, h, l); Ah[c4 + 1][r] = h; Al[c4 + 1][r] = l;
            split2(v.z, h, l); Ah[c4 + 2][r] = h; Al[c4 + 2][r] = l;
            split2(v.w, h, l); Ah[c4 + 3][r] = h; Al[c4 + 3][r] = l;
        }
        // stage B: 16 k x 64 n
        {
            int kr = tid >> 4, c4 = (tid & 15) * 4;
            float4 v = *(const float4*)&B[(size_t)(k0 + kr) * 512 + col0 + c4];
            float4 hv, lv;
            split2(v.x, hv.x, lv.x);
            split2(v.y, hv.y, lv.y);
            split2(v.z, hv.z, lv.z);
            split2(v.w, hv.w, lv.w);
            *(float4*)&Bh[kr][c4] = hv;
            *(float4*)&Bl[kr][c4] = lv;
        }
        __syncthreads();

#pragma unroll
        for (int ks = 0; ks < 2; ks++) {
            const int kk = ks * 8;
            uint32_t ah[2][4], al[2][4];
#pragma unroll
            for (int mt = 0; mt < 2; mt++) {
                int r = wrow + mt * 16;
                ah[mt][0] = __float_as_uint(Ah[kk + tg][r + g]);
                ah[mt][1] = __float_as_uint(Ah[kk + tg][r + g + 8]);
                ah[mt][2] = __float_as_uint(Ah[kk + tg + 4][r + g]);
                ah[mt][3] = __float_as_uint(Ah[kk + tg + 4][r + g + 8]);
                al[mt][0] = __float_as_uint(Al[kk + tg][r + g]);
                al[mt][1] = __float_as_uint(Al[kk + tg][r + g + 8]);
                al[mt][2] = __float_as_uint(Al[kk + tg + 4][r + g]);
                al[mt][3] = __float_as_uint(Al[kk + tg + 4][r + g + 8]);
            }
            uint32_t bh[4][2], bl[4][2];
#pragma unroll
            for (int nt = 0; nt < 4; nt++) {
                int c = wcol + nt * 8;
                bh[nt][0] = __float_as_uint(Bh[kk + tg][c + g]);
                bh[nt][1] = __float_as_uint(Bh[kk + tg + 4][c + g]);
                bl[nt][0] = __float_as_uint(Bl[kk + tg][c + g]);
                bl[nt][1] = __float_as_uint(Bl[kk + tg + 4][c + g]);
            }
#pragma unroll
            for (int mt = 0; mt < 2; mt++)
#pragma unroll
                for (int nt = 0; nt < 4; nt++) {
                    mma_tf32(acc[mt][nt], al[mt], bh[nt]);
                    mma_tf32(acc[mt][nt], ah[mt], bl[nt]);
                    mma_tf32(acc[mt][nt], ah[mt], bh[nt]);
                }
        }
        __syncthreads();
    }

#pragma unroll
    for (int mt = 0; mt < 2; mt++) {
        int r0 = row0 + wrow + mt * 16 + g;
#pragma unroll
        for (int nt = 0; nt < 4; nt++) {
            int c = col0 + wcol + nt * 8 + 2 * tg;
            float b0v = bias[c], b1v = bias[c + 1];
            if (r0 < M) {
                float2 o = make_float2(acc[mt][nt][0] + b0v, acc[mt][nt][1] + b1v);
                *(float2*)&C[(size_t)r0 * 512 + c] = o;
            }
            if (r0 + 8 < M) {
                float2 o = make_float2(acc[mt][nt][2] + b0v, acc[mt][nt][3] + b1v);
                *(float2*)&C[(size_t)(r0 + 8) * 512 + c] = o;
            }
        }
    }
}

// ---------------------------------------------------------------------------
// Gate dot products
// ---------------------------------------------------------------------------
__global__ __launch_bounds__(128) void gate_kernel(const float* __restrict__ wg)
{
    const int row = blockIdx.x;
    const int tid = threadIdx.x;
    float sq = 0.f, sk = 0.f;
#pragma unroll
    for (int e = tid; e < 512; e += 128) {
        sq += g_q[(size_t)row * 512 + e] * wg[e];
        sk += g_k[(size_t)row * 512 + e] * wg[512 + e];
    }
#pragma unroll
    for (int off = 16; off >= 1; off >>= 1) {
        sq += __shfl_down_sync(0xffffffffu, sq, off);
        sk += __shfl_down_sync(0xffffffffu, sk, off);
    }
    __shared__ float pq[4], pk[4];
    if ((tid & 31) == 0) { pq[tid >> 5] = sq; pk[tid >> 5] = sk; }
    __syncthreads();
    if (tid == 0) {
        g_gq[row] = pq[0] + pq[1] + pq[2] + pq[3];
        g_gk[row] = pk[0] + pk[1] + pk[2] + pk[3];
    }
}

// ---------------------------------------------------------------------------
// TF32 mma.sync flash attention v2
// Tq=128 (4 warps x 32 rows), Tk=64, D=64. 128 threads, occ 2.
// Swizzled smem: word(r,d) = r*64 + (pcol(d) ^ ((r&7)<<3)); all fragment
// loads are conflict-free LDS.64.
// ---------------------------------------------------------------------------
#define ATTN_SMEM ((24576 + 64 + 16) * 4)

__global__ __launch_bounds__(128, 2) void attn_mma_kernel(const float* __restrict__ bg_ptr)
{
    extern __shared__ float sm[];
    float* Qs    = sm;             // 128x64 swizzled
    float* Ks    = sm + 8192;      // 64x64 swizzled
    float* Vt    = sm + 12288;     // 64x64 swizzled (transposed: row=d, col=j)
    float* Ps    = sm + 16384;     // 128x64 swizzled
    float* egk_s = sm + 24576;     // 64

    const int qb = blockIdx.x, h = blockIdx.y, b = blockIdx.z;
    const int q0 = qb * 128;
    const int tid = threadIdx.x;
    const int lane = tid & 31;
    const int g = lane >> 2, tg = lane & 3;
    const int wr = (tid >> 5) * 32;
    const int xg = g << 3;
    const float bg = bg_ptr[0];

    const float* qp = g_q + ((size_t)(b * SS)) * EE + h * 64;
    const float* kp = g_k + ((size_t)(b * SS)) * EE + h * 64;
    const float* vp = g_v + ((size_t)(b * SS)) * EE + h * 64;

    // ---- stage Q (tf32, swizzled) ----
#pragma unroll
    for (int it = 0; it < 16; it++) {
        int idx = it * 128 + tid;
        int r = idx >> 4, c4 = (idx & 15) * 4;
        int gi = q0 + r;
        float4 v = make_float4(0.f, 0.f, 0.f, 0.f);
        if (gi < SS) v = *(const float4*)(qp + (size_t)gi * EE + c4);
        int pc = ((c4 >> 3) << 3) + ((c4 >> 2) & 1);
        int xr = (r & 7) << 3;
        float* qrow = Qs + r * 64;
        qrow[(pc + 0) ^ xr] = tf32r(v.x);
        qrow[(pc + 2) ^ xr] = tf32r(v.y);
        qrow[(pc + 4) ^ xr] = tf32r(v.z);
        qrow[(pc + 6) ^ xr] = tf32r(v.w);
    }

    // egq = exp(-gq) for this thread's 4 rows
    float egq[2][2];
#pragma unroll
    for (int mt = 0; mt < 2; mt++)
#pragma unroll
        for (int hf = 0; hf < 2; hf++) {
            int gi = q0 + wr + mt * 16 + g + hf * 8;
            egq[mt][hf] = __expf(-((gi < SS) ? g_gq[b * SS + gi] : 0.f));
        }

    float oacc[2][8][4];
#pragma unroll
    for (int mt = 0; mt < 2; mt++)
#pragma unroll
        for (int nt = 0; nt < 8; nt++)
#pragma unroll
            for (int e = 0; e < 4; e++) oacc[mt][nt][e] = 0.f;
    float lacc[2][2] = {{0.f, 0.f}, {0.f, 0.f}};

    const float C1 = SCALE * LOG2E;
    const float C2 = BIASC * LOG2E;

    int kstart = q0 - WINW; if (kstart < 0) kstart = 0;
    int kend = q0 + 128 + WINW; if (kend > SS) kend = SS;

    for (int k0 = kstart; k0 < kend; k0 += 64) {
        __syncthreads();
        // ---- stage K (swizzled) and V (transposed, swizzled) ----
#pragma unroll
        for (int it = 0; it < 8; it++) {
            int idx = it * 128 + tid;
            int r = idx >> 4, c4 = (idx & 15) * 4;
            int gj = k0 + r;
            float4 kv = make_float4(0.f, 0.f, 0.f, 0.f);
            float4 vv = make_float4(0.f, 0.f, 0.f, 0.f);
            if (gj < SS) {
                kv = *(const float4*)(kp + (size_t)gj * EE + c4);
                vv = *(const float4*)(vp + (size_t)gj * EE + c4);
            }
            int pc = ((c4 >> 3) << 3) + ((c4 >> 2) & 1);
            int xr = (r & 7) << 3;
            float* krow = Ks + r * 64;
            krow[(pc + 0) ^ xr] = tf32r(kv.x);
            krow[(pc + 2) ^ xr] = tf32r(kv.y);
            krow[(pc + 4) ^ xr] = tf32r(kv.z);
            krow[(pc + 6) ^ xr] = tf32r(kv.w);
            int pr = pcol(r);
            Vt[(c4 + 0) * 64 + (pr ^ ((((c4 + 0)) & 7) << 3))] = tf32r(vv.x);
            Vt[(c4 + 1) * 64 + (pr ^ ((((c4 + 1)) & 7) << 3))] = tf32r(vv.y);
            Vt[(c4 + 2) * 64 + (pr ^ ((((c4 + 2)) & 7) << 3))] = tf32r(vv.z);
            Vt[(c4 + 3) * 64 + (pr ^ ((((c4 + 3)) & 7) << 3))] = tf32r(vv.w);
        }
        if (tid < 64) {
            int gj = k0 + tid;
            float gk = (gj < SS) ? g_gk[b * SS + gj] : 0.f;
            egk_s[tid] = __expf(-gk - bg);
        }
        __syncthreads();

        // ---- S = Q @ K^T ----
        float sacc[2][8][4];
#pragma unroll
        for (int mt = 0; mt < 2; mt++)
#pragma unroll
            for (int nt = 0; nt < 8; nt++)
#pragma unroll
                for (int e = 0; e < 4; e++) sacc[mt][nt][e] = 0.f;
#pragma unroll
        for (int kk = 0; kk < 8; kk++) {
            const int cc = (kk * 8 + 2 * tg) ^ xg;
            uint32_t qa[2][4];
#pragma unroll
            for (int mt = 0; mt < 2; mt++) {
                int r = wr + mt * 16 + g;
                float2 lo = *(float2*)&Qs[r * 64 + cc];
                float2 hi = *(float2*)&Qs[(r + 8) * 64 + cc];
                qa[mt][0] = __float_as_uint(lo.x);
                qa[mt][1] = __float_as_uint(hi.x);
                qa[mt][2] = __float_as_uint(lo.y);
                qa[mt][3] = __float_as_uint(hi.y);
            }
#pragma unroll
            for (int nt = 0; nt < 8; nt++) {
                float2 bv = *(float2*)&Ks[(nt * 8 + g) * 64 + cc];
                uint32_t bf[2];
                bf[0] = __float_as_uint(bv.x);
                bf[1] = __float_as_uint(bv.y);
                mma_tf32(sacc[0][nt], qa[0], bf);
                mma_tf32(sacc[1][nt], qa[1], bf);
            }
        }

        // ---- epilogue: gate + bias + mask + exp; P -> smem (tf32) ----
#pragma unroll
        for (int nt = 0; nt < 8; nt++) {
            int lj = nt * 8 + 2 * tg;
            float2 eg = *(float2*)&egk_s[lj];
            int gj0 = k0 + lj, gj1 = gj0 + 1;
            int pc0 = (nt * 8 + (((2 * tg) & 3) << 1) + (tg >> 1)) ^ xg;
#pragma unroll
            for (int mt = 0; mt < 2; mt++) {
                int r0 = wr + mt * 16 + g;
                int gi0 = q0 + r0, gi1 = gi0 + 8;
                int d00 = gi0 - gj0, d01 = gi0 - gj1;
                int d10 = gi1 - gj0, d11 = gi1 - gj1;
                float p00, p01, p10, p11;
                {
                    float gate = rcpf(fmaf(egq[mt][0], eg.x, 1.f));
                    float p = ex2f((sacc[mt][nt][0] * C1 + (float)(d00 * d00) * C2) * gate);
                    p00 = (gj0 < SS && d00 <= WINW && d00 >= -WINW) ? tf32r(p) : 0.f;
                }
                {
                    float gate = rcpf(fmaf(egq[mt][0], eg.y, 1.f));
                    float p = ex2f((sacc[mt][nt][1] * C1 + (float)(d01 * d01) * C2) * gate);
                    p01 = (gj1 < SS && d01 <= WINW && d01 >= -WINW) ? tf32r(p) : 0.f;
                }
                {
                    float gate = rcpf(fmaf(egq[mt][1], eg.x, 1.f));
                    float p = ex2f((sacc[mt][nt][2] * C1 + (float)(d10 * d10) * C2) * gate);
                    p10 = (gj0 < SS && d10 <= WINW && d10 >= -WINW) ? tf32r(p) : 0.f;
                }
                {
                    float gate = rcpf(fmaf(egq[mt][1], eg.y, 1.f));
                    float p = ex2f((sacc[mt][nt][3] * C1 + (float)(d11 * d11) * C2) * gate);
                    p11 = (gj1 < SS && d11 <= WINW && d11 >= -WINW) ? tf32r(p) : 0.f;
                }
                lacc[mt][0] += p00 + p01;
                lacc[mt][1] += p10 + p11;
                float* prow0 = Ps + r0 * 64;
                float* prow1 = Ps + (r0 + 8) * 64;
                prow0[pc0] = p00;
                prow0[pc0 + 2] = p01;
                prow1[pc0] = p10;
                prow1[pc0 + 2] = p11;
            }
        }
        __syncwarp();

        // ---- O += P @ V ----
#pragma unroll
        for (int kk = 0; kk < 8; kk++) {
            const int cc = (kk * 8 + 2 * tg) ^ xg;
            uint32_t pa[2][4];
#pragma unroll
            for (int mt = 0; mt < 2; mt++) {
                int r = wr + mt * 16 + g;
                float2 lo = *(float2*)&Ps[r * 64 + cc];
                float2 hi = *(float2*)&Ps[(r + 8) * 64 + cc];
                pa[mt][0] = __float_as_uint(lo.x);
                pa[mt][1] = __float_as_uint(hi.x);
                pa[mt][2] = __float_as_uint(lo.y);
                pa[mt][3] = __float_as_uint(hi.y);
            }
#pragma unroll
            for (int nt = 0; nt < 8; nt++) {
                float2 bv = *(float2*)&Vt[(nt * 8 + g) * 64 + cc];
                uint32_t bf[2];
                bf[0] = __float_as_uint(bv.x);
                bf[1] = __float_as_uint(bv.y);
                mma_tf32(oacc[0][nt], pa[0], bf);
                mma_tf32(oacc[1][nt], pa[1], bf);
            }
        }
    }

    // ---- final: quad-reduce l, divide, write ----
    float inv[2][2];
#pragma unroll
    for (int mt = 0; mt < 2; mt++)
#pragma unroll
        for (int hf = 0; hf < 2; hf++) {
            float v = lacc[mt][hf];
            v += __shfl_xor_sync(0xffffffffu, v, 1);
            v += __shfl_xor_sync(0xffffffffu, v, 2);
            inv[mt][hf] = rcpf(v);
        }
    float* op = g_ao + ((size_t)(b * SS)) * EE + h * 64;
#pragma unroll
    for (int mt = 0; mt < 2; mt++) {
        int gi0 = q0 + wr + mt * 16 + g;
        int gi1 = gi0 + 8;
        if (gi0 < SS) {
            float iv = inv[mt][0];
#pragma unroll
            for (int nt = 0; nt < 8; nt++) {
                int c = nt * 8 + 2 * tg;
                *(float2*)&op[(size_t)gi0 * EE + c] =
                    make_float2(oacc[mt][nt][0] * iv, oacc[mt][nt][1] * iv);
            }
        }
        if (gi1 < SS) {
            float iv = inv[mt][1];
#pragma unroll
            for (int nt = 0; nt < 8; nt++) {
                int c = nt * 8 + 2 * tg;
                *(float2*)&op[(size_t)gi1 * EE + c] =
                    make_float2(oacc[mt][nt][2] * iv, oacc[mt][nt][3] * iv);
            }
        }
    }
}

// ---------------------------------------------------------------------------
extern "C" void kernel_launch(void* const* d_in, const int* in_sizes, int n_in,
                              void* d_out, int out_size)
{
    const float* x  = (const float*)d_in[0];
    const float* Wq = (const float*)d_in[1];
    const float* bq = (const float*)d_in[2];
    const float* Wk = (const float*)d_in[3];
    const float* bk = (const float*)d_in[4];
    const float* Wv = (const float*)d_in[5];
    const float* bv = (const float*)d_in[6];
    const float* Wo = (const float*)d_in[7];
    const float* bo = (const float*)d_in[8];
    const float* wg = (const float*)d_in[9];
    const float* bg = (const float*)d_in[10];
    float* out = (float*)d_out;

    float *pq, *pk, *pv, *pao;
    cudaGetSymbolAddress((void**)&pq, g_q);
    cudaGetSymbolAddress((void**)&pk, g_k);
    cudaGetSymbolAddress((void**)&pv, g_v);
    cudaGetSymbolAddress((void**)&pao, g_ao);

    cudaFuncSetAttribute(attn_mma_kernel,
                         cudaFuncAttributeMaxDynamicSharedMemorySize, ATTN_SMEM);

    dim3 ggemm(8, 33);   // 512/64=8, ceil(4098/128)=33
    gemm_tc_kernel<<<ggemm, 256>>>(x, Wq, bq, pq, MROWS);
    gemm_tc_kernel<<<ggemm, 256>>>(x, Wk, bk, pk, MROWS);
    gemm_tc_kernel<<<ggemm, 256>>>(x, Wv, bv, pv, MROWS);
    gate_kernel<<<MROWS, 128>>>(wg);
    attn_mma_kernel<<<dim3(17, HH, BB), 128, ATTN_SMEM>>>(bg);
    gemm_tc_kernel<<<ggemm, 256>>>(pao, Wo, bo, out, MROWS);
}

// round 5
// speedup vs baseline: 1.3326x; 1.3326x over previous
#include <cuda_runtime.h>
#include <cstdint>
#include <math.h>

#define BB 2
#define SS 2049
#define EE 512
#define HH 8
#define WINW 1024
#define MROWS (BB * SS)                  // 4098
#define SCALE 0.125f                     // D^-0.5
#define BIASC (-1.9073486328125e-6f)     // -0.5/(512^2)
#define LOG2E 1.4426950408889634f

// Scratch (device globals: no allocation allowed)
__device__ float g_q[MROWS * EE];
__device__ float g_k[MROWS * EE];
__device__ float g_v[MROWS * EE];
__device__ float g_ao[MROWS * EE];
__device__ float g_gq[MROWS];
__device__ float g_gk[MROWS];

// ============================================================================
// helpers
// ============================================================================
__device__ __forceinline__ float tf32r(float x) {
    uint32_t u;
    asm("cvt.rna.tf32.f32 %0, %1;" : "=r"(u) : "f"(x));
    return __uint_as_float(u);
}
__device__ __forceinline__ void split2(float x, float& hi, float& lo) {
    hi = tf32r(x);
    lo = tf32r(x - hi);
}
__device__ __forceinline__ void mma_tf32(float* d, const uint32_t* a, const uint32_t* b) {
    asm volatile(
        "mma.sync.aligned.m16n8k8.row.col.f32.tf32.tf32.f32 "
        "{%0,%1,%2,%3}, {%4,%5,%6,%7}, {%8,%9}, {%0,%1,%2,%3};"
        : "+f"(d[0]), "+f"(d[1]), "+f"(d[2]), "+f"(d[3])
        : "r"(a[0]), "r"(a[1]), "r"(a[2]), "r"(a[3]), "r"(b[0]), "r"(b[1]));
}
__device__ __forceinline__ float rcpf(float x) {
    float r;
    asm("rcp.approx.f32 %0, %1;" : "=f"(r) : "f"(x));
    return r;
}
__device__ __forceinline__ float ex2f(float x) {
    float r;
    asm("ex2.approx.f32 %0, %1;" : "=f"(r) : "f"(x));
    return r;
}

// ---------------------------------------------------------------------------
// 3xTF32 GEMM body: C[M,512] = A[M,512] @ B[512,512] + bias
// BM=128 BN=128 BK=16, 256 threads (8 warps: 4M x 2N), warp tile 32x64
// ---------------------------------------------------------------------------
#define GSTR 136
__device__ __forceinline__ void gemm_body(
    const float* __restrict__ A, const float* __restrict__ B,
    const float* __restrict__ bias, float* __restrict__ C, int M,
    int row0, int col0)
{
    __shared__ float Ah[16][GSTR], Al[16][GSTR];
    __shared__ float Bh[16][GSTR], Bl[16][GSTR];

    const int tid = threadIdx.x;
    const int wid = tid >> 5, lane = tid & 31;
    const int g = lane >> 2, tg = lane & 3;
    const int wm = wid >> 1, wn = wid & 1;
    const int wrow = wm * 32, wcol = wn * 64;

    float acc[2][8][4];
#pragma unroll
    for (int mt = 0; mt < 2; mt++)
#pragma unroll
        for (int nt = 0; nt < 8; nt++)
#pragma unroll
            for (int e = 0; e < 4; e++) acc[mt][nt][e] = 0.f;

    for (int k0 = 0; k0 < 512; k0 += 16) {
#pragma unroll
        for (int it = 0; it < 2; it++) {
            int idx = it * 256 + tid;
            {   // A: [128 rows][16 cols] -> Ah/Al[k][m]
                int r = idx >> 2, c4 = (idx & 3) * 4;
                float4 v = make_float4(0.f, 0.f, 0.f, 0.f);
                if (row0 + r < M)
                    v = *(const float4*)&A[(size_t)(row0 + r) * 512 + k0 + c4];
                float h, l;
                split2(v.x, h, l); Ah[c4 + 0][r] = h; Al[c4 + 0][r] = l;
                split2(v.y, h, l); Ah[c4 + 1][r] = h; Al[c4 + 1][r] = l;
                split2(v.z, h, l); Ah[c4 + 2][r] = h; Al[c4 + 2][r] = l;
                split2(v.w, h, l); Ah[c4 + 3][r] = h; Al[c4 + 3][r] = l;
            }
            {   // B: [16 k][128 n] -> Bh/Bl[k][n]
                int kr = idx >> 5, c32 = (idx & 31) * 4;
                float4 v = *(const float4*)&B[(size_t)(k0 + kr) * 512 + col0 + c32];
                float4 hv, lv;
                split2(v.x, hv.x, lv.x);
                split2(v.y, hv.y, lv.y);
                split2(v.z, hv.z, lv.z);
                split2(v.w, hv.w, lv.w);
                *(float4*)&Bh[kr][c32] = hv;
                *(float4*)&Bl[kr][c32] = lv;
            }
        }
        __syncthreads();

#pragma unroll
        for (int ks = 0; ks < 2; ks++) {
            const int kk = ks * 8;
            uint32_t ah[2][4], al[2][4];
#pragma unroll
            for (int mt = 0; mt < 2; mt++) {
                int r = wrow + mt * 16;
                ah[mt][0] = __float_as_uint(Ah[kk + tg][r + g]);
                ah[mt][1] = __float_as_uint(Ah[kk + tg][r + g + 8]);
                ah[mt][2] = __float_as_uint(Ah[kk + tg + 4][r + g]);
                ah[mt][3] = __float_as_uint(Ah[kk + tg + 4][r + g + 8]);
                al[mt][0] = __float_as_uint(Al[kk + tg][r + g]);
                al[mt][1] = __float_as_uint(Al[kk + tg][r + g + 8]);
                al[mt][2] = __float_as_uint(Al[kk + tg + 4][r + g]);
                al[mt][3] = __float_as_uint(Al[kk + tg + 4][r + g + 8]);
            }
            uint32_t bh[8][2], bl[8][2];
#pragma unroll
            for (int nt = 0; nt < 8; nt++) {
                int c = wcol + nt * 8;
                bh[nt][0] = __float_as_uint(Bh[kk + tg][c + g]);
                bh[nt][1] = __float_as_uint(Bh[kk + tg + 4][c + g]);
                bl[nt][0] = __float_as_uint(Bl[kk + tg][c + g]);
                bl[nt][1] = __float_as_uint(Bl[kk + tg + 4][c + g]);
            }
#pragma unroll
            for (int mt = 0; mt < 2; mt++)
#pragma unroll
                for (int nt = 0; nt < 8; nt++) {
                    mma_tf32(acc[mt][nt], al[mt], bh[nt]);
                    mma_tf32(acc[mt][nt], ah[mt], bl[nt]);
                    mma_tf32(acc[mt][nt], ah[mt], bh[nt]);
                }
        }
        __syncthreads();
    }

#pragma unroll
    for (int mt = 0; mt < 2; mt++) {
        int r0 = row0 + wrow + mt * 16 + g;
#pragma unroll
        for (int nt = 0; nt < 8; nt++) {
            int c = col0 + wcol + nt * 8 + 2 * tg;
            float b0v = bias[c], b1v = bias[c + 1];
            if (r0 < M) {
                float2 o = make_float2(acc[mt][nt][0] + b0v, acc[mt][nt][1] + b1v);
                *(float2*)&C[(size_t)r0 * 512 + c] = o;
            }
            if (r0 + 8 < M) {
                float2 o = make_float2(acc[mt][nt][2] + b0v, acc[mt][nt][3] + b1v);
                *(float2*)&C[(size_t)(r0 + 8) * 512 + c] = o;
            }
        }
    }
}

// Fused QKV projection: blockIdx.z selects {q,k,v}
__global__ __launch_bounds__(256, 1) void qkv_gemm_kernel(
    const float* __restrict__ A,
    const float* __restrict__ Wq, const float* __restrict__ bq,
    const float* __restrict__ Wk, const float* __restrict__ bk,
    const float* __restrict__ Wv, const float* __restrict__ bv,
    float* __restrict__ Cq, float* __restrict__ Ck, float* __restrict__ Cv,
    int M)
{
    const float* B;
    const float* bias;
    float* C;
    if (blockIdx.z == 0)      { B = Wq; bias = bq; C = Cq; }
    else if (blockIdx.z == 1) { B = Wk; bias = bk; C = Ck; }
    else                      { B = Wv; bias = bv; C = Cv; }
    gemm_body(A, B, bias, C, M, blockIdx.y * 128, blockIdx.x * 128);
}

__global__ __launch_bounds__(256, 1) void gemm_tc_kernel(
    const float* __restrict__ A, const float* __restrict__ B,
    const float* __restrict__ bias, float* __restrict__ C, int M)
{
    gemm_body(A, B, bias, C, M, blockIdx.y * 128, blockIdx.x * 128);
}

// ---------------------------------------------------------------------------
// Gate dot products
// ---------------------------------------------------------------------------
__global__ __launch_bounds__(128) void gate_kernel(const float* __restrict__ wg)
{
    const int row = blockIdx.x;
    const int tid = threadIdx.x;
    float sq = 0.f, sk = 0.f;
#pragma unroll
    for (int e = tid; e < 512; e += 128) {
        sq += g_q[(size_t)row * 512 + e] * wg[e];
        sk += g_k[(size_t)row * 512 + e] * wg[512 + e];
    }
#pragma unroll
    for (int off = 16; off >= 1; off >>= 1) {
        sq += __shfl_down_sync(0xffffffffu, sq, off);
        sk += __shfl_down_sync(0xffffffffu, sk, off);
    }
    __shared__ float pq[4], pk[4];
    if ((tid & 31) == 0) { pq[tid >> 5] = sq; pk[tid >> 5] = sk; }
    __syncthreads();
    if (tid == 0) {
        g_gq[row] = pq[0] + pq[1] + pq[2] + pq[3];
        g_gk[row] = pk[0] + pk[1] + pk[2] + pk[3];
    }
}

// ---------------------------------------------------------------------------
// TF32 mma.sync flash attention (R3 version — known 442us config)
// Tq=64, Tk=64, D=64. 128 threads = 4 warps; warp owns 16 q-rows.
// ---------------------------------------------------------------------------
#define ASTR 68
#define ATTN_SMEM (4 * 64 * ASTR * 4 + 256)

__global__ __launch_bounds__(128, 2) void attn_mma_kernel(const float* __restrict__ bg_ptr)
{
    extern __shared__ char smem[];
    float (*Qs)[ASTR] = (float(*)[ASTR])(smem);
    float (*Ks)[ASTR] = (float(*)[ASTR])(smem + 64 * ASTR * 4);
    float (*Vs)[ASTR] = (float(*)[ASTR])(smem + 2 * 64 * ASTR * 4);
    float (*Ps)[ASTR] = (float(*)[ASTR])(smem + 3 * 64 * ASTR * 4);
    float* egk_s = (float*)(smem + 4 * 64 * ASTR * 4);   // 64 floats

    const int qb = blockIdx.x, h = blockIdx.y, b = blockIdx.z;
    const int q0 = qb * 64;
    const int tid = threadIdx.x;
    const int lane = tid & 31;
    const int g = lane >> 2, tg = lane & 3;
    const int wrow = (tid >> 5) * 16;
    const float bg = bg_ptr[0];

    const float* qp = g_q + ((size_t)(b * SS)) * EE + h * 64;
    const float* kp = g_k + ((size_t)(b * SS)) * EE + h * 64;
    const float* vp = g_v + ((size_t)(b * SS)) * EE + h * 64;

    // Stage Q (tf32)
#pragma unroll
    for (int it = 0; it < 8; it++) {
        int idx = it * 128 + tid;
        int r = idx >> 4, c4 = (idx & 15) * 4;
        int gi = q0 + r;
        float4 v = make_float4(0.f, 0.f, 0.f, 0.f);
        if (gi < SS) v = *(const float4*)(qp + (size_t)gi * EE + c4);
        Qs[r][c4 + 0] = tf32r(v.x);
        Qs[r][c4 + 1] = tf32r(v.y);
        Qs[r][c4 + 2] = tf32r(v.z);
        Qs[r][c4 + 3] = tf32r(v.w);
    }
    __syncthreads();

    // Hoist Q A-fragments into registers (reused for all k-tiles)
    uint32_t qa[8][4];
#pragma unroll
    for (int kk = 0; kk < 8; kk++) {
        qa[kk][0] = __float_as_uint(Qs[wrow + g][kk * 8 + tg]);
        qa[kk][1] = __float_as_uint(Qs[wrow + g + 8][kk * 8 + tg]);
        qa[kk][2] = __float_as_uint(Qs[wrow + g][kk * 8 + tg + 4]);
        qa[kk][3] = __float_as_uint(Qs[wrow + g + 8][kk * 8 + tg + 4]);
    }
    const int gi0 = q0 + wrow + g, gi1 = gi0 + 8;
    const float egq0 = __expf(-((gi0 < SS) ? g_gq[b * SS + gi0] : 0.f));
    const float egq1 = __expf(-((gi1 < SS) ? g_gq[b * SS + gi1] : 0.f));

    float oacc[8][4];
#pragma unroll
    for (int nt = 0; nt < 8; nt++)
#pragma unroll
        for (int e = 0; e < 4; e++) oacc[nt][e] = 0.f;
    float l0 = 0.f, l1 = 0.f;

    const float C1 = SCALE * LOG2E;
    const float C2 = BIASC * LOG2E;

    int kstart = q0 - WINW; if (kstart < 0) kstart = 0;
    int kend = q0 + 64 + WINW; if (kend > SS) kend = SS;

    for (int k0 = kstart; k0 < kend; k0 += 64) {
        __syncthreads();
        // Stage K, V (tf32) + exp(-gk - bg)
#pragma unroll
        for (int it = 0; it < 8; it++) {
            int idx = it * 128 + tid;
            int r = idx >> 4, c4 = (idx & 15) * 4;
            int gj = k0 + r;
            float4 kv = make_float4(0.f, 0.f, 0.f, 0.f);
            float4 vv = make_float4(0.f, 0.f, 0.f, 0.f);
            if (gj < SS) {
                kv = *(const float4*)(kp + (size_t)gj * EE + c4);
                vv = *(const float4*)(vp + (size_t)gj * EE + c4);
            }
            Ks[r][c4 + 0] = tf32r(kv.x);
            Ks[r][c4 + 1] = tf32r(kv.y);
            Ks[r][c4 + 2] = tf32r(kv.z);
            Ks[r][c4 + 3] = tf32r(kv.w);
            Vs[r][c4 + 0] = tf32r(vv.x);
            Vs[r][c4 + 1] = tf32r(vv.y);
            Vs[r][c4 + 2] = tf32r(vv.z);
            Vs[r][c4 + 3] = tf32r(vv.w);
        }
        if (tid < 64) {
            int gj = k0 + tid;
            float gk = (gj < SS) ? g_gk[b * SS + gj] : 0.f;
            egk_s[tid] = __expf(-gk - bg);
        }
        __syncthreads();

        // ---- S = Q @ K^T ----
        float sacc[8][4];
#pragma unroll
        for (int nt = 0; nt < 8; nt++)
#pragma unroll
            for (int e = 0; e < 4; e++) sacc[nt][e] = 0.f;
#pragma unroll
        for (int kk = 0; kk < 8; kk++) {
#pragma unroll
            for (int nt = 0; nt < 8; nt++) {
                uint32_t bf[2];
                bf[0] = __float_as_uint(Ks[nt * 8 + g][kk * 8 + tg]);
                bf[1] = __float_as_uint(Ks[nt * 8 + g][kk * 8 + tg + 4]);
                mma_tf32(sacc[nt], qa[kk], bf);
            }
        }

        // ---- Epilogue: gate + bias + mask + exp; P -> smem (tf32) ----
        float lt0 = 0.f, lt1 = 0.f;
#pragma unroll
        for (int nt = 0; nt < 8; nt++) {
            int lj = nt * 8 + 2 * tg;
            float2 eg = *(float2*)&egk_s[lj];
            int gj0 = k0 + lj, gj1 = gj0 + 1;

            int d00 = gi0 - gj0, d01 = gi0 - gj1, d10 = gi1 - gj0, d11 = gi1 - gj1;
            float p00, p01, p10, p11;
            {
                float gate = rcpf(fmaf(egq0, eg.x, 1.f));
                float p = ex2f((sacc[nt][0] * C1 + (float)(d00 * d00) * C2) * gate);
                p00 = (gj0 < SS && d00 <= WINW && d00 >= -WINW) ? tf32r(p) : 0.f;
            }
            {
                float gate = rcpf(fmaf(egq0, eg.y, 1.f));
                float p = ex2f((sacc[nt][1] * C1 + (float)(d01 * d01) * C2) * gate);
                p01 = (gj1 < SS && d01 <= WINW && d01 >= -WINW) ? tf32r(p) : 0.f;
            }
            {
                float gate = rcpf(fmaf(egq1, eg.x, 1.f));
                float p = ex2f((sacc[nt][2] * C1 + (float)(d10 * d10) * C2) * gate);
                p10 = (gj0 < SS && d10 <= WINW && d10 >= -WINW) ? tf32r(p) : 0.f;
            }
            {
                float gate = rcpf(fmaf(egq1, eg.y, 1.f));
                float p = ex2f((sacc[nt][3] * C1 + (float)(d11 * d11) * C2) * gate);
                p11 = (gj1 < SS && d11 <= WINW && d11 >= -WINW) ? tf32r(p) : 0.f;
            }
            lt0 += p00 + p01;
            lt1 += p10 + p11;
            *(float2*)&Ps[wrow + g][lj] = make_float2(p00, p01);
            *(float2*)&Ps[wrow + g + 8][lj] = make_float2(p10, p11);
        }
        lt0 += __shfl_xor_sync(0xffffffffu, lt0, 1);
        lt0 += __shfl_xor_sync(0xffffffffu, lt0, 2);
        lt1 += __shfl_xor_sync(0xffffffffu, lt1, 1);
        lt1 += __shfl_xor_sync(0xffffffffu, lt1, 2);
        l0 += lt0;
        l1 += lt1;
        __syncwarp();

        // ---- O += P @ V ----
#pragma unroll
        for (int kk = 0; kk < 8; kk++) {
            uint32_t pa[4];
            pa[0] = __float_as_uint(Ps[wrow + g][kk * 8 + tg]);
            pa[1] = __float_as_uint(Ps[wrow + g + 8][kk * 8 + tg]);
            pa[2] = __float_as_uint(Ps[wrow + g][kk * 8 + tg + 4]);
            pa[3] = __float_as_uint(Ps[wrow + g + 8][kk * 8 + tg + 4]);
#pragma unroll
            for (int nt = 0; nt < 8; nt++) {
                uint32_t bf[2];
                bf[0] = __float_as_uint(Vs[kk * 8 + tg][nt * 8 + g]);
                bf[1] = __float_as_uint(Vs[kk * 8 + tg + 4][nt * 8 + g]);
                mma_tf32(oacc[nt], pa, bf);
            }
        }
    }

    // ---- Final: O / l -> g_ao ----
    const float inv0 = rcpf(l0), inv1 = rcpf(l1);
    float* op = g_ao + ((size_t)(b * SS)) * EE + h * 64;
#pragma unroll
    for (int nt = 0; nt < 8; nt++) {
        int c = nt * 8 + 2 * tg;
        if (gi0 < SS)
            *(float2*)&op[(size_t)gi0 * EE + c] =
                make_float2(oacc[nt][0] * inv0, oacc[nt][1] * inv0);
        if (gi1 < SS)
            *(float2*)&op[(size_t)gi1 * EE + c] =
                make_float2(oacc[nt][2] * inv1, oacc[nt][3] * inv1);
    }
}

// ---------------------------------------------------------------------------
extern "C" void kernel_launch(void* const* d_in, const int* in_sizes, int n_in,
                              void* d_out, int out_size)
{
    const float* x  = (const float*)d_in[0];
    const float* Wq = (const float*)d_in[1];
    const float* bq = (const float*)d_in[2];
    const float* Wk = (const float*)d_in[3];
    const float* bk = (const float*)d_in[4];
    const float* Wv = (const float*)d_in[5];
    const float* bv = (const float*)d_in[6];
    const float* Wo = (const float*)d_in[7];
    const float* bo = (const float*)d_in[8];
    const float* wg = (const float*)d_in[9];
    const float* bg = (const float*)d_in[10];
    float* out = (float*)d_out;

    float *pq, *pk, *pv, *pao;
    cudaGetSymbolAddress((void**)&pq, g_q);
    cudaGetSymbolAddress((void**)&pk, g_k);
    cudaGetSymbolAddress((void**)&pv, g_v);
    cudaGetSymbolAddress((void**)&pao, g_ao);

    cudaFuncSetAttribute(attn_mma_kernel,
                         cudaFuncAttributeMaxDynamicSharedMemorySize, ATTN_SMEM);

    dim3 gqkv(4, 33, 3);   // fused QKV: z selects projection
    qkv_gemm_kernel<<<gqkv, 256>>>(x, Wq, bq, Wk, bk, Wv, bv, pq, pk, pv, MROWS);
    gate_kernel<<<MROWS, 128>>>(wg);
    attn_mma_kernel<<<dim3(33, HH, BB), 128, ATTN_SMEM>>>(bg);
    gemm_tc_kernel<<<dim3(4, 33), 256>>>(pao, Wo, bo, out, MROWS);
}

// round 6
// speedup vs baseline: 1.3889x; 1.0422x over previous
#include <cuda_runtime.h>
#include <cstdint>
#include <math.h>

#define BB 2
#define SS 2049
#define EE 512
#define HH 8
#define WINW 1024
#define MROWS (BB * SS)                  // 4098
#define SCALE 0.125f                     // D^-0.5
#define BIASC (-1.9073486328125e-6f)     // -0.5/(512^2)
#define LOG2E 1.4426950408889634f

// Scratch (device globals: no allocation allowed)
__device__ float g_q[MROWS * EE];
__device__ float g_k[MROWS * EE];
__device__ float g_v[MROWS * EE];
__device__ float g_ao[MROWS * EE];
__device__ float g_gq[MROWS];
__device__ float g_gk[MROWS];

// ============================================================================
// helpers
// ============================================================================
__device__ __forceinline__ float tf32r(float x) {
    uint32_t u;
    asm("cvt.rna.tf32.f32 %0, %1;" : "=r"(u) : "f"(x));
    return __uint_as_float(u);
}
__device__ __forceinline__ void split2(float x, float& hi, float& lo) {
    hi = tf32r(x);
    lo = tf32r(x - hi);
}
__device__ __forceinline__ void mma_tf32(float* d, const uint32_t* a, const uint32_t* b) {
    asm volatile(
        "mma.sync.aligned.m16n8k8.row.col.f32.tf32.tf32.f32 "
        "{%0,%1,%2,%3}, {%4,%5,%6,%7}, {%8,%9}, {%0,%1,%2,%3};"
        : "+f"(d[0]), "+f"(d[1]), "+f"(d[2]), "+f"(d[3])
        : "r"(a[0]), "r"(a[1]), "r"(a[2]), "r"(a[3]), "r"(b[0]), "r"(b[1]));
}
__device__ __forceinline__ float rcpf(float x) {
    float r;
    asm("rcp.approx.f32 %0, %1;" : "=f"(r) : "f"(x));
    return r;
}
__device__ __forceinline__ float ex2f(float x) {
    float r;
    asm("ex2.approx.f32 %0, %1;" : "=f"(r) : "f"(x));
    return r;
}

// ---------------------------------------------------------------------------
// 3xTF32 GEMM body, software-pipelined double-buffered.
// C[M,512] = A[M,512] @ B[512,512] + bias
// BM=128 BN=128 BK=16, 256 threads (8 warps: 4M x 2N), warp tile 32x64
// ---------------------------------------------------------------------------
#define GSTR 136
#define TILEF (16 * GSTR)                 // floats per tile buffer
#define GEMM_SMEM (8 * TILEF * 4)         // 2 bufs x 4 arrays = 69632 bytes

__device__ __forceinline__ void gemm_body(
    const float* __restrict__ A, const float* __restrict__ B,
    const float* __restrict__ bias, float* __restrict__ C, int M,
    int row0, int col0, float* sm)
{
    float* Ah = sm;                  // [2][16][GSTR]
    float* Al = sm + 2 * TILEF;
    float* Bh = sm + 4 * TILEF;
    float* Bl = sm + 6 * TILEF;

    const int tid = threadIdx.x;
    const int wid = tid >> 5, lane = tid & 31;
    const int g = lane >> 2, tg = lane & 3;
    const int wm = wid >> 1, wn = wid & 1;
    const int wrow = wm * 32, wcol = wn * 64;

    // per-thread staging coords
    const int a_r0 = tid >> 2, a_c = (tid & 3) * 4;          // +64 rows for it=1
    const int b_k0 = tid >> 5, b_c = (tid & 31) * 4;         // +8 k for it=1

    float acc[2][8][4];
#pragma unroll
    for (int mt = 0; mt < 2; mt++)
#pragma unroll
        for (int nt = 0; nt < 8; nt++)
#pragma unroll
            for (int e = 0; e < 4; e++) acc[mt][nt][e] = 0.f;

    float4 pa[2], pb[2];

    // ---- LDG tile k0 into regs ----
#define G_LDG(K0)                                                              \
    {                                                                          \
        _Pragma("unroll")                                                      \
        for (int it = 0; it < 2; it++) {                                       \
            int r = a_r0 + it * 64;                                            \
            pa[it] = make_float4(0.f, 0.f, 0.f, 0.f);                          \
            if (row0 + r < M)                                                  \
                pa[it] = *(const float4*)&A[(size_t)(row0 + r) * 512 + (K0) + a_c]; \
            int kr = b_k0 + it * 8;                                            \
            pb[it] = *(const float4*)&B[(size_t)((K0) + kr) * 512 + col0 + b_c];    \
        }                                                                      \
    }

    // ---- split regs -> smem buffer q ----
#define G_STS(Q)                                                               \
    {                                                                          \
        float* ah = Ah + (Q) * TILEF; float* al = Al + (Q) * TILEF;            \
        float* bh = Bh + (Q) * TILEF; float* bl = Bl + (Q) * TILEF;            \
        _Pragma("unroll")                                                      \
        for (int it = 0; it < 2; it++) {                                       \
            int r = a_r0 + it * 64;                                            \
            float h, l;                                                        \
            split2(pa[it].x, h, l); ah[(a_c + 0) * GSTR + r] = h; al[(a_c + 0) * GSTR + r] = l; \
            split2(pa[it].y, h, l); ah[(a_c + 1) * GSTR + r] = h; al[(a_c + 1) * GSTR + r] = l; \
            split2(pa[it].z, h, l); ah[(a_c + 2) * GSTR + r] = h; al[(a_c + 2) * GSTR + r] = l; \
            split2(pa[it].w, h, l); ah[(a_c + 3) * GSTR + r] = h; al[(a_c + 3) * GSTR + r] = l; \
            int kr = b_k0 + it * 8;                                            \
            float4 hv, lv;                                                     \
            split2(pb[it].x, hv.x, lv.x);                                      \
            split2(pb[it].y, hv.y, lv.y);                                      \
            split2(pb[it].z, hv.z, lv.z);                                      \
            split2(pb[it].w, hv.w, lv.w);                                      \
            *(float4*)&bh[kr * GSTR + b_c] = hv;                               \
            *(float4*)&bl[kr * GSTR + b_c] = lv;                               \
        }                                                                      \
    }

    // prologue: tile0 -> buf0, tile1 -> regs
    G_LDG(0);
    G_STS(0);
    G_LDG(16);
    __syncthreads();

    int p = 0;
    for (int k0 = 0; k0 < 512; k0 += 16) {
        // ---- pipeline: stage next tile, prefetch next-next ----
        if (k0 + 16 < 512) {
            G_STS(1 - p);
            if (k0 + 32 < 512) G_LDG(k0 + 32);
        }

        // ---- compute on buffer p ----
        const float* ah_ = Ah + p * TILEF;
        const float* al_ = Al + p * TILEF;
        const float* bh_ = Bh + p * TILEF;
        const float* bl_ = Bl + p * TILEF;
#pragma unroll
        for (int ks = 0; ks < 2; ks++) {
            const int kk = ks * 8;
            uint32_t ah[2][4], al[2][4];
#pragma unroll
            for (int mt = 0; mt < 2; mt++) {
                int r = wrow + mt * 16;
                ah[mt][0] = __float_as_uint(ah_[(kk + tg) * GSTR + r + g]);
                ah[mt][1] = __float_as_uint(ah_[(kk + tg) * GSTR + r + g + 8]);
                ah[mt][2] = __float_as_uint(ah_[(kk + tg + 4) * GSTR + r + g]);
                ah[mt][3] = __float_as_uint(ah_[(kk + tg + 4) * GSTR + r + g + 8]);
                al[mt][0] = __float_as_uint(al_[(kk + tg) * GSTR + r + g]);
                al[mt][1] = __float_as_uint(al_[(kk + tg) * GSTR + r + g + 8]);
                al[mt][2] = __float_as_uint(al_[(kk + tg + 4) * GSTR + r + g]);
                al[mt][3] = __float_as_uint(al_[(kk + tg + 4) * GSTR + r + g + 8]);
            }
            uint32_t bh[8][2], bl[8][2];
#pragma unroll
            for (int nt = 0; nt < 8; nt++) {
                int c = wcol + nt * 8;
                bh[nt][0] = __float_as_uint(bh_[(kk + tg) * GSTR + c + g]);
                bh[nt][1] = __float_as_uint(bh_[(kk + tg + 4) * GSTR + c + g]);
                bl[nt][0] = __float_as_uint(bl_[(kk + tg) * GSTR + c + g]);
                bl[nt][1] = __float_as_uint(bl_[(kk + tg + 4) * GSTR + c + g]);
            }
#pragma unroll
            for (int mt = 0; mt < 2; mt++)
#pragma unroll
                for (int nt = 0; nt < 8; nt++) {
                    mma_tf32(acc[mt][nt], al[mt], bh[nt]);
                    mma_tf32(acc[mt][nt], ah[mt], bl[nt]);
                    mma_tf32(acc[mt][nt], ah[mt], bh[nt]);
                }
        }

        if (k0 + 16 < 512) {
            __syncthreads();
            p ^= 1;
        }
    }

#pragma unroll
    for (int mt = 0; mt < 2; mt++) {
        int r0 = row0 + wrow + mt * 16 + g;
#pragma unroll
        for (int nt = 0; nt < 8; nt++) {
            int c = col0 + wcol + nt * 8 + 2 * tg;
            float b0v = bias[c], b1v = bias[c + 1];
            if (r0 < M) {
                float2 o = make_float2(acc[mt][nt][0] + b0v, acc[mt][nt][1] + b1v);
                *(float2*)&C[(size_t)r0 * 512 + c] = o;
            }
            if (r0 + 8 < M) {
                float2 o = make_float2(acc[mt][nt][2] + b0v, acc[mt][nt][3] + b1v);
                *(float2*)&C[(size_t)(r0 + 8) * 512 + c] = o;
            }
        }
    }
#undef G_LDG
#undef G_STS
}

// Fused QKV projection: blockIdx.z selects {q,k,v}
__global__ __launch_bounds__(256, 1) void qkv_gemm_kernel(
    const float* __restrict__ A,
    const float* __restrict__ Wq, const float* __restrict__ bq,
    const float* __restrict__ Wk, const float* __restrict__ bk,
    const float* __restrict__ Wv, const float* __restrict__ bv,
    float* __restrict__ Cq, float* __restrict__ Ck, float* __restrict__ Cv,
    int M)
{
    extern __shared__ float gsm[];
    const float* B;
    const float* bias;
    float* C;
    if (blockIdx.z == 0)      { B = Wq; bias = bq; C = Cq; }
    else if (blockIdx.z == 1) { B = Wk; bias = bk; C = Ck; }
    else                      { B = Wv; bias = bv; C = Cv; }
    gemm_body(A, B, bias, C, M, blockIdx.y * 128, blockIdx.x * 128, gsm);
}

__global__ __launch_bounds__(256, 1) void gemm_tc_kernel(
    const float* __restrict__ A, const float* __restrict__ B,
    const float* __restrict__ bias, float* __restrict__ C, int M)
{
    extern __shared__ float gsm[];
    gemm_body(A, B, bias, C, M, blockIdx.y * 128, blockIdx.x * 128, gsm);
}

// ---------------------------------------------------------------------------
// Gate dot products
// ---------------------------------------------------------------------------
__global__ __launch_bounds__(128) void gate_kernel(const float* __restrict__ wg)
{
    const int row = blockIdx.x;
    const int tid = threadIdx.x;
    float sq = 0.f, sk = 0.f;
#pragma unroll
    for (int e = tid; e < 512; e += 128) {
        sq += g_q[(size_t)row * 512 + e] * wg[e];
        sk += g_k[(size_t)row * 512 + e] * wg[512 + e];
    }
#pragma unroll
    for (int off = 16; off >= 1; off >>= 1) {
        sq += __shfl_down_sync(0xffffffffu, sq, off);
        sk += __shfl_down_sync(0xffffffffu, sk, off);
    }
    __shared__ float pq[4], pk[4];
    if ((tid & 31) == 0) { pq[tid >> 5] = sq; pk[tid >> 5] = sk; }
    __syncthreads();
    if (tid == 0) {
        g_gq[row] = pq[0] + pq[1] + pq[2] + pq[3];
        g_gk[row] = pk[0] + pk[1] + pk[2] + pk[3];
    }
}

// ---------------------------------------------------------------------------
// TF32 mma.sync flash attention (R3 config — unchanged this round)
// Tq=64, Tk=64, D=64. 128 threads = 4 warps; warp owns 16 q-rows.
// ---------------------------------------------------------------------------
#define ASTR 68
#define ATTN_SMEM (4 * 64 * ASTR * 4 + 256)

__global__ __launch_bounds__(128, 2) void attn_mma_kernel(const float* __restrict__ bg_ptr)
{
    extern __shared__ char smem[];
    float (*Qs)[ASTR] = (float(*)[ASTR])(smem);
    float (*Ks)[ASTR] = (float(*)[ASTR])(smem + 64 * ASTR * 4);
    float (*Vs)[ASTR] = (float(*)[ASTR])(smem + 2 * 64 * ASTR * 4);
    float (*Ps)[ASTR] = (float(*)[ASTR])(smem + 3 * 64 * ASTR * 4);
    float* egk_s = (float*)(smem + 4 * 64 * ASTR * 4);   // 64 floats

    const int qb = blockIdx.x, h = blockIdx.y, b = blockIdx.z;
    const int q0 = qb * 64;
    const int tid = threadIdx.x;
    const int lane = tid & 31;
    const int g = lane >> 2, tg = lane & 3;
    const int wrow = (tid >> 5) * 16;
    const float bg = bg_ptr[0];

    const float* qp = g_q + ((size_t)(b * SS)) * EE + h * 64;
    const float* kp = g_k + ((size_t)(b * SS)) * EE + h * 64;
    const float* vp = g_v + ((size_t)(b * SS)) * EE + h * 64;

    // Stage Q (tf32)
#pragma unroll
    for (int it = 0; it < 8; it++) {
        int idx = it * 128 + tid;
        int r = idx >> 4, c4 = (idx & 15) * 4;
        int gi = q0 + r;
        float4 v = make_float4(0.f, 0.f, 0.f, 0.f);
        if (gi < SS) v = *(const float4*)(qp + (size_t)gi * EE + c4);
        Qs[r][c4 + 0] = tf32r(v.x);
        Qs[r][c4 + 1] = tf32r(v.y);
        Qs[r][c4 + 2] = tf32r(v.z);
        Qs[r][c4 + 3] = tf32r(v.w);
    }
    __syncthreads();

    // Hoist Q A-fragments into registers (reused for all k-tiles)
    uint32_t qa[8][4];
#pragma unroll
    for (int kk = 0; kk < 8; kk++) {
        qa[kk][0] = __float_as_uint(Qs[wrow + g][kk * 8 + tg]);
        qa[kk][1] = __float_as_uint(Qs[wrow + g + 8][kk * 8 + tg]);
        qa[kk][2] = __float_as_uint(Qs[wrow + g][kk * 8 + tg + 4]);
        qa[kk][3] = __float_as_uint(Qs[wrow + g + 8][kk * 8 + tg + 4]);
    }
    const int gi0 = q0 + wrow + g, gi1 = gi0 + 8;
    const float egq0 = __expf(-((gi0 < SS) ? g_gq[b * SS + gi0] : 0.f));
    const float egq1 = __expf(-((gi1 < SS) ? g_gq[b * SS + gi1] : 0.f));

    float oacc[8][4];
#pragma unroll
    for (int nt = 0; nt < 8; nt++)
#pragma unroll
        for (int e = 0; e < 4; e++) oacc[nt][e] = 0.f;
    float l0 = 0.f, l1 = 0.f;

    const float C1 = SCALE * LOG2E;
    const float C2 = BIASC * LOG2E;

    int kstart = q0 - WINW; if (kstart < 0) kstart = 0;
    int kend = q0 + 64 + WINW; if (kend > SS) kend = SS;

    for (int k0 = kstart; k0 < kend; k0 += 64) {
        __syncthreads();
        // Stage K, V (tf32) + exp(-gk - bg)
#pragma unroll
        for (int it = 0; it < 8; it++) {
            int idx = it * 128 + tid;
            int r = idx >> 4, c4 = (idx & 15) * 4;
            int gj = k0 + r;
            float4 kv = make_float4(0.f, 0.f, 0.f, 0.f);
            float4 vv = make_float4(0.f, 0.f, 0.f, 0.f);
            if (gj < SS) {
                kv = *(const float4*)(kp + (size_t)gj * EE + c4);
                vv = *(const float4*)(vp + (size_t)gj * EE + c4);
            }
            Ks[r][c4 + 0] = tf32r(kv.x);
            Ks[r][c4 + 1] = tf32r(kv.y);
            Ks[r][c4 + 2] = tf32r(kv.z);
            Ks[r][c4 + 3] = tf32r(kv.w);
            Vs[r][c4 + 0] = tf32r(vv.x);
            Vs[r][c4 + 1] = tf32r(vv.y);
            Vs[r][c4 + 2] = tf32r(vv.z);
            Vs[r][c4 + 3] = tf32r(vv.w);
        }
        if (tid < 64) {
            int gj = k0 + tid;
            float gk = (gj < SS) ? g_gk[b * SS + gj] : 0.f;
            egk_s[tid] = __expf(-gk - bg);
        }
        __syncthreads();

        // ---- S = Q @ K^T ----
        float sacc[8][4];
#pragma unroll
        for (int nt = 0; nt < 8; nt++)
#pragma unroll
            for (int e = 0; e < 4; e++) sacc[nt][e] = 0.f;
#pragma unroll
        for (int kk = 0; kk < 8; kk++) {
#pragma unroll
            for (int nt = 0; nt < 8; nt++) {
                uint32_t bf[2];
                bf[0] = __float_as_uint(Ks[nt * 8 + g][kk * 8 + tg]);
                bf[1] = __float_as_uint(Ks[nt * 8 + g][kk * 8 + tg + 4]);
                mma_tf32(sacc[nt], qa[kk], bf);
            }
        }

        // ---- Epilogue: gate + bias + mask + exp; P -> smem (tf32) ----
        float lt0 = 0.f, lt1 = 0.f;
#pragma unroll
        for (int nt = 0; nt < 8; nt++) {
            int lj = nt * 8 + 2 * tg;
            float2 eg = *(float2*)&egk_s[lj];
            int gj0 = k0 + lj, gj1 = gj0 + 1;

            int d00 = gi0 - gj0, d01 = gi0 - gj1, d10 = gi1 - gj0, d11 = gi1 - gj1;
            float p00, p01, p10, p11;
            {
                float gate = rcpf(fmaf(egq0, eg.x, 1.f));
                float p = ex2f((sacc[nt][0] * C1 + (float)(d00 * d00) * C2) * gate);
                p00 = (gj0 < SS && d00 <= WINW && d00 >= -WINW) ? tf32r(p) : 0.f;
            }
            {
                float gate = rcpf(fmaf(egq0, eg.y, 1.f));
                float p = ex2f((sacc[nt][1] * C1 + (float)(d01 * d01) * C2) * gate);
                p01 = (gj1 < SS && d01 <= WINW && d01 >= -WINW) ? tf32r(p) : 0.f;
            }
            {
                float gate = rcpf(fmaf(egq1, eg.x, 1.f));
                float p = ex2f((sacc[nt][2] * C1 + (float)(d10 * d10) * C2) * gate);
                p10 = (gj0 < SS && d10 <= WINW && d10 >= -WINW) ? tf32r(p) : 0.f;
            }
            {
                float gate = rcpf(fmaf(egq1, eg.y, 1.f));
                float p = ex2f((sacc[nt][3] * C1 + (float)(d11 * d11) * C2) * gate);
                p11 = (gj1 < SS && d11 <= WINW && d11 >= -WINW) ? tf32r(p) : 0.f;
            }
            lt0 += p00 + p01;
            lt1 += p10 + p11;
            *(float2*)&Ps[wrow + g][lj] = make_float2(p00, p01);
            *(float2*)&Ps[wrow + g + 8][lj] = make_float2(p10, p11);
        }
        lt0 += __shfl_xor_sync(0xffffffffu, lt0, 1);
        lt0 += __shfl_xor_sync(0xffffffffu, lt0, 2);
        lt1 += __shfl_xor_sync(0xffffffffu, lt1, 1);
        lt1 += __shfl_xor_sync(0xffffffffu, lt1, 2);
        l0 += lt0;
        l1 += lt1;
        __syncwarp();

        // ---- O += P @ V ----
#pragma unroll
        for (int kk = 0; kk < 8; kk++) {
            uint32_t pa[4];
            pa[0] = __float_as_uint(Ps[wrow + g][kk * 8 + tg]);
            pa[1] = __float_as_uint(Ps[wrow + g + 8][kk * 8 + tg]);
            pa[2] = __float_as_uint(Ps[wrow + g][kk * 8 + tg + 4]);
            pa[3] = __float_as_uint(Ps[wrow + g + 8][kk * 8 + tg + 4]);
#pragma unroll
            for (int nt = 0; nt < 8; nt++) {
                uint32_t bf[2];
                bf[0] = __float_as_uint(Vs[kk * 8 + tg][nt * 8 + g]);
                bf[1] = __float_as_uint(Vs[kk * 8 + tg + 4][nt * 8 + g]);
                mma_tf32(oacc[nt], pa, bf);
            }
        }
    }

    // ---- Final: O / l -> g_ao ----
    const float inv0 = rcpf(l0), inv1 = rcpf(l1);
    float* op = g_ao + ((size_t)(b * SS)) * EE + h * 64;
#pragma unroll
    for (int nt = 0; nt < 8; nt++) {
        int c = nt * 8 + 2 * tg;
        if (gi0 < SS)
            *(float2*)&op[(size_t)gi0 * EE + c] =
                make_float2(oacc[nt][0] * inv0, oacc[nt][1] * inv0);
        if (gi1 < SS)
            *(float2*)&op[(size_t)gi1 * EE + c] =
                make_float2(oacc[nt][2] * inv1, oacc[nt][3] * inv1);
    }
}

// ---------------------------------------------------------------------------
extern "C" void kernel_launch(void* const* d_in, const int* in_sizes, int n_in,
                              void* d_out, int out_size)
{
    const float* x  = (const float*)d_in[0];
    const float* Wq = (const float*)d_in[1];
    const float* bq = (const float*)d_in[2];
    const float* Wk = (const float*)d_in[3];
    const float* bk = (const float*)d_in[4];
    const float* Wv = (const float*)d_in[5];
    const float* bv = (const float*)d_in[6];
    const float* Wo = (const float*)d_in[7];
    const float* bo = (const float*)d_in[8];
    const float* wg = (const float*)d_in[9];
    const float* bg = (const float*)d_in[10];
    float* out = (float*)d_out;

    float *pq, *pk, *pv, *pao;
    cudaGetSymbolAddress((void**)&pq, g_q);
    cudaGetSymbolAddress((void**)&pk, g_k);
    cudaGetSymbolAddress((void**)&pv, g_v);
    cudaGetSymbolAddress((void**)&pao, g_ao);

    cudaFuncSetAttribute(attn_mma_kernel,
                         cudaFuncAttributeMaxDynamicSharedMemorySize, ATTN_SMEM);
    cudaFuncSetAttribute(qkv_gemm_kernel,
                         cudaFuncAttributeMaxDynamicSharedMemorySize, GEMM_SMEM);
    cudaFuncSetAttribute(gemm_tc_kernel,
                         cudaFuncAttributeMaxDynamicSharedMemorySize, GEMM_SMEM);

    dim3 gqkv(4, 33, 3);   // fused QKV: z selects projection
    qkv_gemm_kernel<<<gqkv, 256, GEMM_SMEM>>>(x, Wq, bq, Wk, bk, Wv, bv, pq, pk, pv, MROWS);
    gate_kernel<<<MROWS, 128>>>(wg);
    attn_mma_kernel<<<dim3(33, HH, BB), 128, ATTN_SMEM>>>(bg);
    gemm_tc_kernel<<<dim3(4, 33), 256, GEMM_SMEM>>>(pao, Wo, bo, out, MROWS);
}

// round 7
// speedup vs baseline: 1.4847x; 1.0690x over previous
#include <cuda_runtime.h>
#include <cuda_pipeline.h>
#include <cstdint>
#include <math.h>

#define BB 2
#define SS 2049
#define EE 512
#define HH 8
#define WINW 1024
#define MROWS (BB * SS)                  // 4098
#define SCALE 0.125f                     // D^-0.5
#define BIASC (-1.9073486328125e-6f)     // -0.5/(512^2)
#define LOG2E 1.4426950408889634f

// Scratch (device globals: no allocation allowed)
__device__ float g_q[MROWS * EE];
__device__ float g_k[MROWS * EE];
__device__ float g_v[MROWS * EE];
__device__ float g_ao[MROWS * EE];
__device__ float g_gq[MROWS];
__device__ float g_gk[MROWS];

// ============================================================================
// helpers
// ============================================================================
__device__ __forceinline__ float tf32r(float x) {
    uint32_t u;
    asm("cvt.rna.tf32.f32 %0, %1;" : "=r"(u) : "f"(x));
    return __uint_as_float(u);
}
__device__ __forceinline__ void split2(float x, float& hi, float& lo) {
    hi = tf32r(x);
    lo = tf32r(x - hi);
}
__device__ __forceinline__ void mma_tf32(float* d, const uint32_t* a, const uint32_t* b) {
    asm volatile(
        "mma.sync.aligned.m16n8k8.row.col.f32.tf32.tf32.f32 "
        "{%0,%1,%2,%3}, {%4,%5,%6,%7}, {%8,%9}, {%0,%1,%2,%3};"
        : "+f"(d[0]), "+f"(d[1]), "+f"(d[2]), "+f"(d[3])
        : "r"(a[0]), "r"(a[1]), "r"(a[2]), "r"(a[3]), "r"(b[0]), "r"(b[1]));
}
__device__ __forceinline__ float rcpf(float x) {
    float r;
    asm("rcp.approx.f32 %0, %1;" : "=f"(r) : "f"(x));
    return r;
}
__device__ __forceinline__ float ex2f(float x) {
    float r;
    asm("ex2.approx.f32 %0, %1;" : "=f"(r) : "f"(x));
    return r;
}

// ---------------------------------------------------------------------------
// 3xTF32 GEMM body, software-pipelined double-buffered. (unchanged from R6)
// ---------------------------------------------------------------------------
#define GSTR 136
#define TILEF (16 * GSTR)
#define GEMM_SMEM (8 * TILEF * 4)

__device__ __forceinline__ void gemm_body(
    const float* __restrict__ A, const float* __restrict__ B,
    const float* __restrict__ bias, float* __restrict__ C, int M,
    int row0, int col0, float* sm)
{
    float* Ah = sm;
    float* Al = sm + 2 * TILEF;
    float* Bh = sm + 4 * TILEF;
    float* Bl = sm + 6 * TILEF;

    const int tid = threadIdx.x;
    const int wid = tid >> 5, lane = tid & 31;
    const int g = lane >> 2, tg = lane & 3;
    const int wm = wid >> 1, wn = wid & 1;
    const int wrow = wm * 32, wcol = wn * 64;

    const int a_r0 = tid >> 2, a_c = (tid & 3) * 4;
    const int b_k0 = tid >> 5, b_c = (tid & 31) * 4;

    float acc[2][8][4];
#pragma unroll
    for (int mt = 0; mt < 2; mt++)
#pragma unroll
        for (int nt = 0; nt < 8; nt++)
#pragma unroll
            for (int e = 0; e < 4; e++) acc[mt][nt][e] = 0.f;

    float4 pa[2], pb[2];

#define G_LDG(K0)                                                              \
    {                                                                          \
        _Pragma("unroll")                                                      \
        for (int it = 0; it < 2; it++) {                                       \
            int r = a_r0 + it * 64;                                            \
            pa[it] = make_float4(0.f, 0.f, 0.f, 0.f);                          \
            if (row0 + r < M)                                                  \
                pa[it] = *(const float4*)&A[(size_t)(row0 + r) * 512 + (K0) + a_c]; \
            int kr = b_k0 + it * 8;                                            \
            pb[it] = *(const float4*)&B[(size_t)((K0) + kr) * 512 + col0 + b_c];    \
        }                                                                      \
    }

#define G_STS(Q)                                                               \
    {                                                                          \
        float* ah = Ah + (Q) * TILEF; float* al = Al + (Q) * TILEF;            \
        float* bh = Bh + (Q) * TILEF; float* bl = Bl + (Q) * TILEF;            \
        _Pragma("unroll")                                                      \
        for (int it = 0; it < 2; it++) {                                       \
            int r = a_r0 + it * 64;                                            \
            float h, l;                                                        \
            split2(pa[it].x, h, l); ah[(a_c + 0) * GSTR + r] = h; al[(a_c + 0) * GSTR + r] = l; \
            split2(pa[it].y, h, l); ah[(a_c + 1) * GSTR + r] = h; al[(a_c + 1) * GSTR + r] = l; \
            split2(pa[it].z, h, l); ah[(a_c + 2) * GSTR + r] = h; al[(a_c + 2) * GSTR + r] = l; \
            split2(pa[it].w, h, l); ah[(a_c + 3) * GSTR + r] = h; al[(a_c + 3) * GSTR + r] = l; \
            int kr = b_k0 + it * 8;                                            \
            float4 hv, lv;                                                     \
            split2(pb[it].x, hv.x, lv.x);                                      \
            split2(pb[it].y, hv.y, lv.y);                                      \
            split2(pb[it].z, hv.z, lv.z);                                      \
            split2(pb[it].w, hv.w, lv.w);                                      \
            *(float4*)&bh[kr * GSTR + b_c] = hv;                               \
            *(float4*)&bl[kr * GSTR + b_c] = lv;                               \
        }                                                                      \
    }

    G_LDG(0);
    G_STS(0);
    G_LDG(16);
    __syncthreads();

    int p = 0;
    for (int k0 = 0; k0 < 512; k0 += 16) {
        if (k0 + 16 < 512) {
            G_STS(1 - p);
            if (k0 + 32 < 512) G_LDG(k0 + 32);
        }

        const float* ah_ = Ah + p * TILEF;
        const float* al_ = Al + p * TILEF;
        const float* bh_ = Bh + p * TILEF;
        const float* bl_ = Bl + p * TILEF;
#pragma unroll
        for (int ks = 0; ks < 2; ks++) {
            const int kk = ks * 8;
            uint32_t ah[2][4], al[2][4];
#pragma unroll
            for (int mt = 0; mt < 2; mt++) {
                int r = wrow + mt * 16;
                ah[mt][0] = __float_as_uint(ah_[(kk + tg) * GSTR + r + g]);
                ah[mt][1] = __float_as_uint(ah_[(kk + tg) * GSTR + r + g + 8]);
                ah[mt][2] = __float_as_uint(ah_[(kk + tg + 4) * GSTR + r + g]);
                ah[mt][3] = __float_as_uint(ah_[(kk + tg + 4) * GSTR + r + g + 8]);
                al[mt][0] = __float_as_uint(al_[(kk + tg) * GSTR + r + g]);
                al[mt][1] = __float_as_uint(al_[(kk + tg) * GSTR + r + g + 8]);
                al[mt][2] = __float_as_uint(al_[(kk + tg + 4) * GSTR + r + g]);
                al[mt][3] = __float_as_uint(al_[(kk + tg + 4) * GSTR + r + g + 8]);
            }
            uint32_t bh[8][2], bl[8][2];
#pragma unroll
            for (int nt = 0; nt < 8; nt++) {
                int c = wcol + nt * 8;
                bh[nt][0] = __float_as_uint(bh_[(kk + tg) * GSTR + c + g]);
                bh[nt][1] = __float_as_uint(bh_[(kk + tg + 4) * GSTR + c + g]);
                bl[nt][0] = __float_as_uint(bl_[(kk + tg) * GSTR + c + g]);
                bl[nt][1] = __float_as_uint(bl_[(kk + tg + 4) * GSTR + c + g]);
            }
#pragma unroll
            for (int mt = 0; mt < 2; mt++)
#pragma unroll
                for (int nt = 0; nt < 8; nt++) {
                    mma_tf32(acc[mt][nt], al[mt], bh[nt]);
                    mma_tf32(acc[mt][nt], ah[mt], bl[nt]);
                    mma_tf32(acc[mt][nt], ah[mt], bh[nt]);
                }
        }

        if (k0 + 16 < 512) {
            __syncthreads();
            p ^= 1;
        }
    }

#pragma unroll
    for (int mt = 0; mt < 2; mt++) {
        int r0 = row0 + wrow + mt * 16 + g;
#pragma unroll
        for (int nt = 0; nt < 8; nt++) {
            int c = col0 + wcol + nt * 8 + 2 * tg;
            float b0v = bias[c], b1v = bias[c + 1];
            if (r0 < M) {
                float2 o = make_float2(acc[mt][nt][0] + b0v, acc[mt][nt][1] + b1v);
                *(float2*)&C[(size_t)r0 * 512 + c] = o;
            }
            if (r0 + 8 < M) {
                float2 o = make_float2(acc[mt][nt][2] + b0v, acc[mt][nt][3] + b1v);
                *(float2*)&C[(size_t)(r0 + 8) * 512 + c] = o;
            }
        }
    }
#undef G_LDG
#undef G_STS
}

__global__ __launch_bounds__(256, 1) void qkv_gemm_kernel(
    const float* __restrict__ A,
    const float* __restrict__ Wq, const float* __restrict__ bq,
    const float* __restrict__ Wk, const float* __restrict__ bk,
    const float* __restrict__ Wv, const float* __restrict__ bv,
    float* __restrict__ Cq, float* __restrict__ Ck, float* __restrict__ Cv,
    int M)
{
    extern __shared__ float gsm[];
    const float* B;
    const float* bias;
    float* C;
    if (blockIdx.z == 0)      { B = Wq; bias = bq; C = Cq; }
    else if (blockIdx.z == 1) { B = Wk; bias = bk; C = Ck; }
    else                      { B = Wv; bias = bv; C = Cv; }
    gemm_body(A, B, bias, C, M, blockIdx.y * 128, blockIdx.x * 128, gsm);
}

__global__ __launch_bounds__(256, 1) void gemm_tc_kernel(
    const float* __restrict__ A, const float* __restrict__ B,
    const float* __restrict__ bias, float* __restrict__ C, int M)
{
    extern __shared__ float gsm[];
    gemm_body(A, B, bias, C, M, blockIdx.y * 128, blockIdx.x * 128, gsm);
}

// ---------------------------------------------------------------------------
// Gate dot products
// ---------------------------------------------------------------------------
__global__ __launch_bounds__(128) void gate_kernel(const float* __restrict__ wg)
{
    const int row = blockIdx.x;
    const int tid = threadIdx.x;
    float sq = 0.f, sk = 0.f;
#pragma unroll
    for (int e = tid; e < 512; e += 128) {
        sq += g_q[(size_t)row * 512 + e] * wg[e];
        sk += g_k[(size_t)row * 512 + e] * wg[512 + e];
    }
#pragma unroll
    for (int off = 16; off >= 1; off >>= 1) {
        sq += __shfl_down_sync(0xffffffffu, sq, off);
        sk += __shfl_down_sync(0xffffffffu, sk, off);
    }
    __shared__ float pq[4], pk[4];
    if ((tid & 31) == 0) { pq[tid >> 5] = sq; pk[tid >> 5] = sk; }
    __syncthreads();
    if (tid == 0) {
        g_gq[row] = pq[0] + pq[1] + pq[2] + pq[3];
        g_gk[row] = pk[0] + pk[1] + pk[2] + pk[3];
    }
}

// ---------------------------------------------------------------------------
// TF32 mma.sync flash attention with cp.async double-buffered K/V staging.
// Tq=64, Tk=64, D=64. 128 threads = 4 warps; warp owns 16 q-rows. occ 2.
// K/V enter smem raw (fp32); mma hardware-truncates to tf32.
// ---------------------------------------------------------------------------
#define ASTR 68
#define TILE68 (64 * ASTR)
// Qs + Ks[2] + Vs[2] + Ps + egk[2][64]
#define ATTN_SMEM ((6 * TILE68 + 128 + 32) * 4)

__global__ __launch_bounds__(128, 2) void attn_mma_kernel(const float* __restrict__ bg_ptr)
{
    extern __shared__ float sm[];
    float* Qs   = sm;                       // [64][ASTR]
    float* Ps   = sm + 5 * TILE68;          // [64][ASTR]
    float* egk  = sm + 6 * TILE68;          // [2][64]

    const int qb = blockIdx.x, h = blockIdx.y, b = blockIdx.z;
    const int q0 = qb * 64;
    const int tid = threadIdx.x;
    const int lane = tid & 31;
    const int g = lane >> 2, tg = lane & 3;
    const int wrow = (tid >> 5) * 16;
    const float bg = bg_ptr[0];

    const float* qp = g_q + ((size_t)(b * SS)) * EE + h * 64;
    const float* kp = g_k + ((size_t)(b * SS)) * EE + h * 64;
    const float* vp = g_v + ((size_t)(b * SS)) * EE + h * 64;

    int kstart = q0 - WINW; if (kstart < 0) kstart = 0;
    int kend = q0 + 64 + WINW; if (kend > SS) kend = SS;

    // cp.async staging of one K/V tile into buffer bb
    const int s_r = tid >> 4, s_c = (tid & 15) * 4;   // + it*8 rows
#define STAGE_KV(K0, BBUF)                                                     \
    {                                                                          \
        float* Kb = sm + (1 + (BBUF)) * TILE68;                                \
        float* Vb = sm + (3 + (BBUF)) * TILE68;                                \
        _Pragma("unroll")                                                      \
        for (int it = 0; it < 8; it++) {                                       \
            int r = s_r + it * 8;                                              \
            int gj = (K0) + r;                                                 \
            size_t off = (size_t)gj * EE + s_c;                                \
            int zf = (gj < SS) ? 0 : 16;                                       \
            __pipeline_memcpy_async(&Kb[r * ASTR + s_c], kp + off, 16, zf);    \
            __pipeline_memcpy_async(&Vb[r * ASTR + s_c], vp + off, 16, zf);    \
        }                                                                      \
        __pipeline_commit();                                                   \
    }

    // prologue: start tile-0 loads immediately
    STAGE_KV(kstart, 0);
    float gk_reg = 0.f;
    if (tid < 64) {
        int gj = kstart + tid;
        gk_reg = (gj < SS) ? g_gk[b * SS + gj] : 0.f;
    }

    // Stage Q (tf32 rna) while tile 0 streams in
#pragma unroll
    for (int it = 0; it < 8; it++) {
        int idx = it * 128 + tid;
        int r = idx >> 4, c4 = (idx & 15) * 4;
        int gi = q0 + r;
        float4 v = make_float4(0.f, 0.f, 0.f, 0.f);
        if (gi < SS) v = *(const float4*)(qp + (size_t)gi * EE + c4);
        Qs[r * ASTR + c4 + 0] = tf32r(v.x);
        Qs[r * ASTR + c4 + 1] = tf32r(v.y);
        Qs[r * ASTR + c4 + 2] = tf32r(v.z);
        Qs[r * ASTR + c4 + 3] = tf32r(v.w);
    }
    __syncthreads();

    // Hoist Q A-fragments into registers (reused for all k-tiles)
    uint32_t qa[8][4];
#pragma unroll
    for (int kk = 0; kk < 8; kk++) {
        qa[kk][0] = __float_as_uint(Qs[(wrow + g) * ASTR + kk * 8 + tg]);
        qa[kk][1] = __float_as_uint(Qs[(wrow + g + 8) * ASTR + kk * 8 + tg]);
        qa[kk][2] = __float_as_uint(Qs[(wrow + g) * ASTR + kk * 8 + tg + 4]);
        qa[kk][3] = __float_as_uint(Qs[(wrow + g + 8) * ASTR + kk * 8 + tg + 4]);
    }
    const int gi0 = q0 + wrow + g, gi1 = gi0 + 8;
    const float egq0 = __expf(-((gi0 < SS) ? g_gq[b * SS + gi0] : 0.f));
    const float egq1 = __expf(-((gi1 < SS) ? g_gq[b * SS + gi1] : 0.f));

    float oacc[8][4];
#pragma unroll
    for (int nt = 0; nt < 8; nt++)
#pragma unroll
        for (int e = 0; e < 4; e++) oacc[nt][e] = 0.f;
    float l0 = 0.f, l1 = 0.f;

    const float C1 = SCALE * LOG2E;
    const float C2 = BIASC * LOG2E;

    int p = 0;
    for (int k0 = kstart; k0 < kend; k0 += 64, p ^= 1) {
        __pipeline_wait_prior(0);      // tile for this iteration landed
        __syncthreads();               // + all threads done with buffer 1-p

        // write this tile's egk (from prefetched reg); kick off next tile
        if (tid < 64) egk[p * 64 + tid] = __expf(-gk_reg - bg);
        if (k0 + 64 < kend) {
            STAGE_KV(k0 + 64, 1 - p);
            if (tid < 64) {
                int gj = k0 + 64 + tid;
                gk_reg = (gj < SS) ? g_gk[b * SS + gj] : 0.f;
            }
        }
        __syncthreads();               // egk visible; buffers settled

        const float* Kb = sm + (1 + p) * TILE68;
        const float* Vb = sm + (3 + p) * TILE68;
        const float* eg_s = egk + p * 64;

        // ---- S = Q @ K^T ----
        float sacc[8][4];
#pragma unroll
        for (int nt = 0; nt < 8; nt++)
#pragma unroll
            for (int e = 0; e < 4; e++) sacc[nt][e] = 0.f;
#pragma unroll
        for (int kk = 0; kk < 8; kk++) {
#pragma unroll
            for (int nt = 0; nt < 8; nt++) {
                uint32_t bf[2];
                bf[0] = __float_as_uint(Kb[(nt * 8 + g) * ASTR + kk * 8 + tg]);
                bf[1] = __float_as_uint(Kb[(nt * 8 + g) * ASTR + kk * 8 + tg + 4]);
                mma_tf32(sacc[nt], qa[kk], bf);
            }
        }

        // ---- Epilogue: gate + bias + mask + exp; P -> smem (tf32) ----
        float lt0 = 0.f, lt1 = 0.f;
#pragma unroll
        for (int nt = 0; nt < 8; nt++) {
            int lj = nt * 8 + 2 * tg;
            float2 eg = *(float2*)&eg_s[lj];
            int gj0 = k0 + lj, gj1 = gj0 + 1;

            int d00 = gi0 - gj0, d01 = gi0 - gj1, d10 = gi1 - gj0, d11 = gi1 - gj1;
            float p00, p01, p10, p11;
            {
                float gate = rcpf(fmaf(egq0, eg.x, 1.f));
                float pe = ex2f((sacc[nt][0] * C1 + (float)(d00 * d00) * C2) * gate);
                p00 = (gj0 < SS && d00 <= WINW && d00 >= -WINW) ? tf32r(pe) : 0.f;
            }
            {
                float gate = rcpf(fmaf(egq0, eg.y, 1.f));
                float pe = ex2f((sacc[nt][1] * C1 + (float)(d01 * d01) * C2) * gate);
                p01 = (gj1 < SS && d01 <= WINW && d01 >= -WINW) ? tf32r(pe) : 0.f;
            }
            {
                float gate = rcpf(fmaf(egq1, eg.x, 1.f));
                float pe = ex2f((sacc[nt][2] * C1 + (float)(d10 * d10) * C2) * gate);
                p10 = (gj0 < SS && d10 <= WINW && d10 >= -WINW) ? tf32r(pe) : 0.f;
            }
            {
                float gate = rcpf(fmaf(egq1, eg.y, 1.f));
                float pe = ex2f((sacc[nt][3] * C1 + (float)(d11 * d11) * C2) * gate);
                p11 = (gj1 < SS && d11 <= WINW && d11 >= -WINW) ? tf32r(pe) : 0.f;
            }
            lt0 += p00 + p01;
            lt1 += p10 + p11;
            *(float2*)&Ps[(wrow + g) * ASTR + lj] = make_float2(p00, p01);
            *(float2*)&Ps[(wrow + g + 8) * ASTR + lj] = make_float2(p10, p11);
        }
        lt0 += __shfl_xor_sync(0xffffffffu, lt0, 1);
        lt0 += __shfl_xor_sync(0xffffffffu, lt0, 2);
        lt1 += __shfl_xor_sync(0xffffffffu, lt1, 1);
        lt1 += __shfl_xor_sync(0xffffffffu, lt1, 2);
        l0 += lt0;
        l1 += lt1;
        __syncwarp();

        // ---- O += P @ V ----
#pragma unroll
        for (int kk = 0; kk < 8; kk++) {
            uint32_t pa[4];
            pa[0] = __float_as_uint(Ps[(wrow + g) * ASTR + kk * 8 + tg]);
            pa[1] = __float_as_uint(Ps[(wrow + g + 8) * ASTR + kk * 8 + tg]);
            pa[2] = __float_as_uint(Ps[(wrow + g) * ASTR + kk * 8 + tg + 4]);
            pa[3] = __float_as_uint(Ps[(wrow + g + 8) * ASTR + kk * 8 + tg + 4]);
#pragma unroll
            for (int nt = 0; nt < 8; nt++) {
                uint32_t bf[2];
                bf[0] = __float_as_uint(Vb[(kk * 8 + tg) * ASTR + nt * 8 + g]);
                bf[1] = __float_as_uint(Vb[(kk * 8 + tg + 4) * ASTR + nt * 8 + g]);
                mma_tf32(oacc[nt], pa, bf);
            }
        }
    }

    // ---- Final: O / l -> g_ao ----
    const float inv0 = rcpf(l0), inv1 = rcpf(l1);
    float* op = g_ao + ((size_t)(b * SS)) * EE + h * 64;
#pragma unroll
    for (int nt = 0; nt < 8; nt++) {
        int c = nt * 8 + 2 * tg;
        if (gi0 < SS)
            *(float2*)&op[(size_t)gi0 * EE + c] =
                make_float2(oacc[nt][0] * inv0, oacc[nt][1] * inv0);
        if (gi1 < SS)
            *(float2*)&op[(size_t)gi1 * EE + c] =
                make_float2(oacc[nt][2] * inv1, oacc[nt][3] * inv1);
    }
#undef STAGE_KV
}

// ---------------------------------------------------------------------------
extern "C" void kernel_launch(void* const* d_in, const int* in_sizes, int n_in,
                              void* d_out, int out_size)
{
    const float* x  = (const float*)d_in[0];
    const float* Wq = (const float*)d_in[1];
    const float* bq = (const float*)d_in[2];
    const float* Wk = (const float*)d_in[3];
    const float* bk = (const float*)d_in[4];
    const float* Wv = (const float*)d_in[5];
    const float* bv = (const float*)d_in[6];
    const float* Wo = (const float*)d_in[7];
    const float* bo = (const float*)d_in[8];
    const float* wg = (const float*)d_in[9];
    const float* bg = (const float*)d_in[10];
    float* out = (float*)d_out;

    float *pq, *pk, *pv, *pao;
    cudaGetSymbolAddress((void**)&pq, g_q);
    cudaGetSymbolAddress((void**)&pk, g_k);
    cudaGetSymbolAddress((void**)&pv, g_v);
    cudaGetSymbolAddress((void**)&pao, g_ao);

    cudaFuncSetAttribute(attn_mma_kernel,
                         cudaFuncAttributeMaxDynamicSharedMemorySize, ATTN_SMEM);
    cudaFuncSetAttribute(qkv_gemm_kernel,
                         cudaFuncAttributeMaxDynamicSharedMemorySize, GEMM_SMEM);
    cudaFuncSetAttribute(gemm_tc_kernel,
                         cudaFuncAttributeMaxDynamicSharedMemorySize, GEMM_SMEM);

    dim3 gqkv(4, 33, 3);   // fused QKV: z selects projection
    qkv_gemm_kernel<<<gqkv, 256, GEMM_SMEM>>>(x, Wq, bq, Wk, bk, Wv, bv, pq, pk, pv, MROWS);
    gate_kernel<<<MROWS, 128>>>(wg);
    attn_mma_kernel<<<dim3(33, HH, BB), 128, ATTN_SMEM>>>(bg);
    gemm_tc_kernel<<<dim3(4, 33), 256, GEMM_SMEM>>>(pao, Wo, bo, out, MROWS);
}